// round 6
// baseline (speedup 1.0000x reference)
#include <cuda_runtime.h>
#include <cuda_bf16.h>
#include <math.h>

#define NN 50000
#define EE 800000
#define ETOT (EE + NN)
#define NB 49              // ceil(NN/1024)
#define EPS 1e-5f

// ---------------- device scratch ----------------
__device__ float d_bufA[NN * 64];
__device__ float d_bufB[NN * 64];
__device__ float d_bufC[NN * 64];
__device__ float d_es[NN * 2];
__device__ float d_ed[NN * 2];
__device__ int   d_cnt[NN];
__device__ int   d_rowptr[NN + 1];
__device__ int   d_cursor[NN];
__device__ int   d_col[ETOT];
__device__ float d_bnacc[320];   // L1:[sum64|sq64] L2:[sum64|sq64] L3:[sum32|sq32]

// ---------------- f32x2 helpers (semantics proven in R5) ----------------
__device__ __forceinline__ void fma2(unsigned long long& d, unsigned long long a,
                                     unsigned long long b) {
    asm("fma.rn.f32x2 %0, %1, %2, %0;" : "+l"(d) : "l"(a), "l"(b));
}
__device__ __forceinline__ unsigned long long pk2(float x) {
    unsigned long long r;
    asm("mov.b64 %0, {%1, %1};" : "=l"(r) : "f"(x));
    return r;
}
union U64F2 { unsigned long long u; float2 f; };

// ---------------- CSR build ----------------
__global__ void count_k(const int* __restrict__ dst) {
    int i = blockIdx.x * 256 + threadIdx.x;
    if (i >= ETOT) return;
    int d = (i < EE) ? __ldg(&dst[i]) : (i - EE);
    atomicAdd(&d_cnt[d], 1);
}

// single-block fused scan: rowptr/cursor from cnt (49 chunks of 1024, running carry)
__global__ void scan_k() {
    __shared__ int wsum[32];
    int tid  = threadIdx.x;
    int lane = tid & 31, wid = tid >> 5;
    int carry = 0;
    for (int chunk = 0; chunk < NB; chunk++) {
        int g = chunk * 1024 + tid;
        int v = (g < NN) ? d_cnt[g] : 0;
        int x = v;
#pragma unroll
        for (int o = 1; o < 32; o <<= 1) {
            int t = __shfl_up_sync(0xffffffffu, x, o);
            if (lane >= o) x += t;
        }
        if (lane == 31) wsum[wid] = x;
        __syncthreads();
        if (wid == 0) {
            int w = wsum[lane];
#pragma unroll
            for (int o = 1; o < 32; o <<= 1) {
                int t = __shfl_up_sync(0xffffffffu, w, o);
                if (lane >= o) w += t;
            }
            wsum[lane] = w;
        }
        __syncthreads();
        int incl = x + (wid ? wsum[wid - 1] : 0);
        int excl = carry + incl - v;
        if (g < NN) { d_rowptr[g] = excl; d_cursor[g] = excl; }
        carry += wsum[31];
        __syncthreads();
    }
    if (tid == 0) d_rowptr[NN] = carry;
}

__global__ void scatter_k(const int* __restrict__ src, const int* __restrict__ dst) {
    int i = blockIdx.x * 256 + threadIdx.x;
    if (i >= ETOT) return;
    int s, d;
    if (i < EE) { s = __ldg(&src[i]); d = __ldg(&dst[i]); }
    else        { s = i - EE; d = s; }
    int pos = atomicAdd(&d_cursor[d], 1);
    d_col[pos] = s;
}

// ---- fused GEMM (f32x2 row-pair, padded k-major staging) + BN input + es/ed ------
// acc[rp][c]: u64 = rows (row0+2rp, row0+2rp+1) at col ct*4+c. x pair loaded as
// natural u64 from 2 consecutive floats of sXT[k][*]; w broadcast via pk2.
template<int K, int NC, bool BN, int H>
__global__ void __launch_bounds__(256) gemm_k(
    const float* __restrict__ X, const float* __restrict__ W,
    const float* __restrict__ asv, const float* __restrict__ adv,
    const float* __restrict__ accIn, const float* __restrict__ g,
    const float* __restrict__ be, float* __restrict__ Hout)
{
    constexpr int KT  = 32;            // K-chunk
    constexpr int CT  = NC / 4;        // col threads: 16 (NC=64) or 8 (NC=32)
    constexpr int RT  = 256 / CT;      // 16 or 32
    constexpr int RPB = RT * 8;        // 128 or 256 rows per block
    constexpr int ST  = RPB + 4;       // padded sXT row stride (floats)

    __shared__ float sXT[KT * ST];     // [k][r]
    __shared__ float sW[KT * NC];      // [k][c]
    __shared__ float sS[BN ? 64 : 1];
    __shared__ float sT[BN ? 64 : 1];

    if (BN) {
        if (threadIdx.x < K) {
            float mu  = accIn[threadIdx.x] * (1.f / NN);
            float var = fmaf(-mu, mu, accIn[K + threadIdx.x] * (1.f / NN));
            float sc  = rsqrtf(var + EPS) * g[threadIdx.x];
            sS[threadIdx.x] = sc;
            sT[threadIdx.x] = be[threadIdx.x] - mu * sc;
        }
    }
    const int ct   = threadIdx.x % CT;
    const int rt   = threadIdx.x / CT;
    const int row0 = rt * 8;
    const int r0   = blockIdx.x * RPB;

    unsigned long long acc[4][4];
#pragma unroll
    for (int i = 0; i < 4; i++)
#pragma unroll
        for (int c = 0; c < 4; c++) acc[i][c] = 0ull;

    for (int kt = 0; kt < K; kt += KT) {
        __syncthreads();
        // stage W chunk [KT x NC]
#pragma unroll
        for (int i = threadIdx.x; i < KT * NC / 4; i += 256) {
            reinterpret_cast<float4*>(sW)[i] =
                __ldg(reinterpret_cast<const float4*>(W) + (size_t)kt * (NC / 4) + i);
        }
        // stage X chunk transposed [KT][RPB] with optional BN+ReLU
#pragma unroll
        for (int i = threadIdx.x; i < RPB * (KT / 4); i += 256) {
            int r = i / (KT / 4), c4 = i % (KT / 4);
            int gr = r0 + r;
            float4 v = make_float4(0.f, 0.f, 0.f, 0.f);
            if (gr < NN)
                v = *reinterpret_cast<const float4*>(X + (size_t)gr * K + kt + c4 * 4);
            if (BN) {
                int kk = kt + c4 * 4;
                v.x = fmaxf(fmaf(v.x, sS[kk + 0], sT[kk + 0]), 0.f);
                v.y = fmaxf(fmaf(v.y, sS[kk + 1], sT[kk + 1]), 0.f);
                v.z = fmaxf(fmaf(v.z, sS[kk + 2], sT[kk + 2]), 0.f);
                v.w = fmaxf(fmaf(v.w, sS[kk + 3], sT[kk + 3]), 0.f);
            }
            sXT[(c4 * 4 + 0) * ST + r] = v.x;
            sXT[(c4 * 4 + 1) * ST + r] = v.y;
            sXT[(c4 * 4 + 2) * ST + r] = v.z;
            sXT[(c4 * 4 + 3) * ST + r] = v.w;
        }
        __syncthreads();
#pragma unroll 4
        for (int k = 0; k < KT; k++) {
            unsigned long long xp0 = *reinterpret_cast<const unsigned long long*>(
                sXT + k * ST + row0 + 0);
            unsigned long long xp1 = *reinterpret_cast<const unsigned long long*>(
                sXT + k * ST + row0 + 2);
            unsigned long long xp2 = *reinterpret_cast<const unsigned long long*>(
                sXT + k * ST + row0 + 4);
            unsigned long long xp3 = *reinterpret_cast<const unsigned long long*>(
                sXT + k * ST + row0 + 6);
            float4 w4 = *reinterpret_cast<const float4*>(sW + k * NC + ct * 4);
            unsigned long long wp0 = pk2(w4.x);
            unsigned long long wp1 = pk2(w4.y);
            unsigned long long wp2 = pk2(w4.z);
            unsigned long long wp3 = pk2(w4.w);
            fma2(acc[0][0], xp0, wp0); fma2(acc[0][1], xp0, wp1);
            fma2(acc[0][2], xp0, wp2); fma2(acc[0][3], xp0, wp3);
            fma2(acc[1][0], xp1, wp0); fma2(acc[1][1], xp1, wp1);
            fma2(acc[1][2], xp1, wp2); fma2(acc[1][3], xp1, wp3);
            fma2(acc[2][0], xp2, wp0); fma2(acc[2][1], xp2, wp1);
            fma2(acc[2][2], xp2, wp2); fma2(acc[2][3], xp2, wp3);
            fma2(acc[3][0], xp3, wp0); fma2(acc[3][1], xp3, wp1);
            fma2(acc[3][2], xp3, wp2); fma2(acc[3][3], xp3, wp3);
        }
    }

    // epilogue: unpack rows, store H, fused es/ed (shfl over ct-lanes of each head)
    float as_[4], ad_[4];
#pragma unroll
    for (int c = 0; c < 4; c++) {
        as_[c] = __ldg(asv + ct * 4 + c);
        ad_[c] = __ldg(adv + ct * 4 + c);
    }
#pragma unroll
    for (int rp = 0; rp < 4; rp++) {
#pragma unroll
        for (int h = 0; h < 2; h++) {
            int gr = r0 + row0 + rp * 2 + h;
            float v[4];
#pragma unroll
            for (int c = 0; c < 4; c++) {
                U64F2 t; t.u = acc[rp][c];
                v[c] = h ? t.f.y : t.f.x;
            }
            float ps = v[0] * as_[0] + v[1] * as_[1] + v[2] * as_[2] + v[3] * as_[3];
            float pd = v[0] * ad_[0] + v[1] * ad_[1] + v[2] * ad_[2] + v[3] * ad_[3];
            // reduce over the 8 ct-lanes of this head (ct bits = lane bits 0..2)
            ps += __shfl_xor_sync(0xffffffffu, ps, 1);
            pd += __shfl_xor_sync(0xffffffffu, pd, 1);
            ps += __shfl_xor_sync(0xffffffffu, ps, 2);
            pd += __shfl_xor_sync(0xffffffffu, pd, 2);
            ps += __shfl_xor_sync(0xffffffffu, ps, 4);
            pd += __shfl_xor_sync(0xffffffffu, pd, 4);
            if (gr < NN) {
                *reinterpret_cast<float4*>(Hout + (size_t)gr * NC + ct * 4) =
                    make_float4(v[0], v[1], v[2], v[3]);
                if (NC == 64) {
                    if (ct == 0) { d_es[gr * 2]     = ps; d_ed[gr * 2]     = pd; }
                    if (ct == 8) { d_es[gr * 2 + 1] = ps; d_ed[gr * 2 + 1] = pd; }
                } else {
                    if (ct == 0) { d_es[gr] = ps; d_ed[gr] = pd; }
                }
            }
        }
    }
}

// -------- GAT aggregation (warp/node) + fused BN stats (smem tree + atomics) ------
__device__ __forceinline__ float lrelu(float x) { return fmaxf(x, 0.2f * x); }

template<int H>
__global__ void __launch_bounds__(512) agg_k(const float* __restrict__ Hm,
                                             const float* __restrict__ bias,
                                             float* __restrict__ out,
                                             float* __restrict__ accOut) {
    __shared__ float red[16][128];
    int w = threadIdx.x >> 5;
    int l = threadIdx.x & 31;
    int node = blockIdx.x * 16 + w;

    if (H == 2) {
        float o0 = 0.f, o1 = 0.f;
        if (node < NN) {
            int beg = __ldg(&d_rowptr[node]);
            int end = __ldg(&d_rowptr[node + 1]);
            const float2 edv = reinterpret_cast<const float2*>(d_ed)[node];
            const float2* es2 = reinterpret_cast<const float2*>(d_es);
            float dn0 = 0.f, dn1 = 0.f, a0 = 0.f, a1 = 0.f;
#pragma unroll 4
            for (int j = beg; j < end; j++) {
                int s = __ldg(&d_col[j]);
                float2 e = __ldg(&es2[s]);
                float p0 = __expf(lrelu(e.x + edv.x));
                float p1 = __expf(lrelu(e.y + edv.y));
                const float* hr = Hm + (size_t)s * 64;
                dn0 += p0; dn1 += p1;
                a0 = fmaf(p0, __ldg(hr + l), a0);
                a1 = fmaf(p1, __ldg(hr + 32 + l), a1);
            }
            o0 = a0 / (dn0 + 1e-16f) + __ldg(bias + l);
            o1 = a1 / (dn1 + 1e-16f) + __ldg(bias + 32 + l);
            out[(size_t)node * 64 + l]      = o0;
            out[(size_t)node * 64 + 32 + l] = o1;
        }
        red[w][l]      = o0;
        red[w][32 + l] = o1;
        red[w][64 + l] = o0 * o0;
        red[w][96 + l] = o1 * o1;
        __syncthreads();
        if (threadIdx.x < 128) {
            float s = 0.f;
#pragma unroll
            for (int i = 0; i < 16; i++) s += red[i][threadIdx.x];
            atomicAdd(&accOut[threadIdx.x], s);
        }
    } else {
        float o = 0.f;
        if (node < NN) {
            int beg = __ldg(&d_rowptr[node]);
            int end = __ldg(&d_rowptr[node + 1]);
            float edv = d_ed[node];
            float dn = 0.f, a = 0.f;
#pragma unroll 4
            for (int j = beg; j < end; j++) {
                int s = __ldg(&d_col[j]);
                float p = __expf(lrelu(__ldg(&d_es[s]) + edv));
                dn += p;
                a = fmaf(p, __ldg(Hm + (size_t)s * 32 + l), a);
            }
            o = a / (dn + 1e-16f) + __ldg(bias + l);
            out[(size_t)node * 32 + l] = o;
        }
        red[w][l]      = o;
        red[w][32 + l] = o * o;
        __syncthreads();
        if (threadIdx.x < 64) {
            float s = 0.f;
#pragma unroll
            for (int i = 0; i < 16; i++) s += red[i][threadIdx.x];
            atomicAdd(&accOut[threadIdx.x], s);
        }
    }
}

// final BN apply + ReLU -> out (stats direct from acc)
__global__ void bnapply3_k(const float* __restrict__ X, const float* __restrict__ acc,
                           const float* __restrict__ g, const float* __restrict__ be,
                           float* __restrict__ Y) {
    int idx = blockIdx.x * 256 + threadIdx.x;
    if (idx >= NN * 32) return;
    int c = idx & 31;
    float mu  = acc[c] * (1.f / NN);
    float var = fmaf(-mu, mu, acc[32 + c] * (1.f / NN));
    float y = (X[idx] - mu) * rsqrtf(var + EPS) * g[c] + be[c];
    Y[idx] = fmaxf(y, 0.f);
}

// ---------------- launch ----------------
static inline int cdiv(int a, int b) { return (a + b - 1) / b; }

extern "C" void kernel_launch(void* const* d_in, const int* in_sizes, int n_in,
                              void* d_out, int out_size) {
    const float* x   = (const float*)d_in[0];
    const float* W1  = (const float*)d_in[1];
    const float* as1 = (const float*)d_in[2];
    const float* ad1 = (const float*)d_in[3];
    const float* b1  = (const float*)d_in[4];
    const float* g1  = (const float*)d_in[5];
    const float* be1 = (const float*)d_in[6];
    const float* W2  = (const float*)d_in[7];
    const float* as2 = (const float*)d_in[8];
    const float* ad2 = (const float*)d_in[9];
    const float* b2  = (const float*)d_in[10];
    const float* g2  = (const float*)d_in[11];
    const float* be2 = (const float*)d_in[12];
    const float* W3  = (const float*)d_in[13];
    const float* as3 = (const float*)d_in[14];
    const float* ad3 = (const float*)d_in[15];
    const float* b3  = (const float*)d_in[16];
    const float* g3  = (const float*)d_in[17];
    const float* be3 = (const float*)d_in[18];
    const int*   ei  = (const int*)d_in[19];
    const int* esrc = ei;
    const int* edst = ei + EE;

    float* bufA; cudaGetSymbolAddress((void**)&bufA, d_bufA);
    float* bufB; cudaGetSymbolAddress((void**)&bufB, d_bufB);
    float* bufC; cudaGetSymbolAddress((void**)&bufC, d_bufC);
    float* bnac; cudaGetSymbolAddress((void**)&bnac, d_bnacc);
    int*   cntp; cudaGetSymbolAddress((void**)&cntp, d_cnt);
    float* outp = (float*)d_out;

    const int aggBlocks = cdiv(NN, 16);   // 3125

    // zero scratch (async memsets are graph-capturable)
    cudaMemsetAsync(cntp, 0, NN * sizeof(int));
    cudaMemsetAsync(bnac, 0, 320 * sizeof(float));

    // CSR build; gemm1 interleaved (independent of CSR)
    count_k<<<cdiv(ETOT, 256), 256>>>(edst);
    gemm_k<128, 64, false, 2><<<cdiv(NN, 128), 256>>>(
        x, W1, as1, ad1, nullptr, nullptr, nullptr, bufB);
    scan_k<<<1, 1024>>>();
    scatter_k<<<cdiv(ETOT, 256), 256>>>(esrc, edst);

    // layer 1 aggregation (+BN1 stats)
    agg_k<2><<<aggBlocks, 512>>>(bufB, b1, bufC, bnac + 0);

    // layer 2 (BN1+ReLU fused into X staging)
    gemm_k<64, 64, true, 2><<<cdiv(NN, 128), 256>>>(
        bufC, W2, as2, ad2, bnac + 0, g1, be1, bufB);
    agg_k<2><<<aggBlocks, 512>>>(bufB, b2, bufC, bnac + 128);

    // layer 3 (BN2+ReLU fused into X staging)
    gemm_k<64, 32, true, 1><<<cdiv(NN, 256), 256>>>(
        bufC, W3, as3, ad3, bnac + 128, g2, be2, bufA);
    agg_k<1><<<aggBlocks, 512>>>(bufA, b3, bufC, bnac + 256);
    bnapply3_k<<<cdiv(NN * 32, 256), 256>>>(bufC, bnac + 256, g3, be3, outp);
}

// round 7
// speedup vs baseline: 1.1845x; 1.1845x over previous
#include <cuda_runtime.h>
#include <cuda_bf16.h>
#include <math.h>

#define NN 50000
#define EE 800000
#define ETOT (EE + NN)
#define NB 49              // ceil(NN/1024)
#define EPS 1e-5f

// ---------------- device scratch ----------------
__device__ float d_bufA[NN * 64];
__device__ float d_bufB[NN * 64];
__device__ float d_bufC[NN * 64];
__device__ float d_es[NN * 2];
__device__ float d_ed[NN * 2];
__device__ int   d_cnt[NN];
__device__ int   d_scan[NN];
__device__ int   d_rowptr[NN + 1];
__device__ int   d_cursor[NN];
__device__ int   d_col[ETOT];
__device__ int   d_btot[NB];
__device__ int   d_boff[NB];
__device__ float d_bnacc[320];   // L1:[sum64|sq64] L2:[sum64|sq64] L3:[sum32|sq32]

// ---------------- CSR build ----------------
__global__ void count_k(const int* __restrict__ dst) {
    int i = blockIdx.x * 256 + threadIdx.x;
    if (i >= ETOT) return;
    int d = (i < EE) ? __ldg(&dst[i]) : (i - EE);
    atomicAdd(&d_cnt[d], 1);
}

__global__ void scan1_k() {
    __shared__ int wsum[32];
    int g = blockIdx.x * 1024 + threadIdx.x;
    int lane = threadIdx.x & 31, wid = threadIdx.x >> 5;
    int v = (g < NN) ? d_cnt[g] : 0;
    int x = v;
#pragma unroll
    for (int o = 1; o < 32; o <<= 1) {
        int t = __shfl_up_sync(0xffffffffu, x, o);
        if (lane >= o) x += t;
    }
    if (lane == 31) wsum[wid] = x;
    __syncthreads();
    if (wid == 0) {
        int w = wsum[lane];
#pragma unroll
        for (int o = 1; o < 32; o <<= 1) {
            int t = __shfl_up_sync(0xffffffffu, w, o);
            if (lane >= o) w += t;
        }
        wsum[lane] = w;
    }
    __syncthreads();
    int incl = x + (wid ? wsum[wid - 1] : 0);
    if (g < NN) d_scan[g] = incl;
    if (threadIdx.x == 1023) d_btot[blockIdx.x] = incl;
}

__global__ void scan2_k() {   // 64 threads, NB=49
    int t = threadIdx.x;
    int lane = t & 31, w = t >> 5;
    int v = (t < NB) ? d_btot[t] : 0;
    int x = v;
#pragma unroll
    for (int o = 1; o < 32; o <<= 1) {
        int s = __shfl_up_sync(0xffffffffu, x, o);
        if (lane >= o) x += s;
    }
    __shared__ int s0;
    if (w == 0 && lane == 31) s0 = x;
    __syncthreads();
    int incl = x + (w ? s0 : 0);
    if (t < NB) d_boff[t] = incl - v;
}

__global__ void scan3_k() {
    int i = blockIdx.x * 256 + threadIdx.x;
    if (i >= NN) return;
    int incl = d_scan[i] + d_boff[i >> 10];
    int excl = incl - d_cnt[i];
    d_rowptr[i] = excl;
    d_cursor[i] = excl;
    if (i == NN - 1) d_rowptr[NN] = incl;
}

__global__ void scatter_k(const int* __restrict__ src, const int* __restrict__ dst) {
    int i = blockIdx.x * 256 + threadIdx.x;
    if (i >= ETOT) return;
    int s, d;
    if (i < EE) { s = __ldg(&src[i]); d = __ldg(&dst[i]); }
    else        { s = i - EE; d = s; }
    int pos = atomicAdd(&d_cursor[d], 1);
    d_col[pos] = s;
}

// ------- fused GEMM (R4-proven scalar core) + BN-from-acc input + es/ed epilogue ----
template<int K, int NC, bool BN, int H>
__global__ void __launch_bounds__(256) gemm_k(
    const float* __restrict__ X, const float* __restrict__ W,
    const float* __restrict__ asv, const float* __restrict__ adv,
    const float* __restrict__ accIn, const float* __restrict__ g,
    const float* __restrict__ be, float* __restrict__ Hout)
{
    constexpr int CT  = NC / 4;        // 16 (NC=64) or 8 (NC=32)
    constexpr int RT  = 256 / CT;      // 16 or 32
    constexpr int RPB = RT * 4;        // 64 or 128 rows per block
    __shared__ float sW[64 * NC];
    __shared__ float sX[RPB * 64];
    __shared__ float sS[BN ? K : 1];
    __shared__ float sT[BN ? K : 1];

    if (BN) {
        if (threadIdx.x < K) {
            float mu  = accIn[threadIdx.x] * (1.f / NN);
            float var = fmaf(-mu, mu, accIn[K + threadIdx.x] * (1.f / NN));
            float sc  = rsqrtf(var + EPS) * g[threadIdx.x];
            sS[threadIdx.x] = sc;
            sT[threadIdx.x] = be[threadIdx.x] - mu * sc;
        }
    }
    const int ct = threadIdx.x % CT;
    const int rt = threadIdx.x / CT;
    const int r0 = blockIdx.x * RPB;
    const int row0 = rt * 4;
    float acc[4][4] = {};

    for (int kt = 0; kt < K; kt += 64) {
        __syncthreads();
#pragma unroll
        for (int i = threadIdx.x; i < 64 * NC / 4; i += 256) {
            reinterpret_cast<float4*>(sW)[i] =
                __ldg(reinterpret_cast<const float4*>(W) + (size_t)kt * (NC / 4) + i);
        }
#pragma unroll
        for (int i = threadIdx.x; i < RPB * 16; i += 256) {
            int r = i >> 4, c4 = i & 15;
            int gr = r0 + r;
            float4 v = make_float4(0.f, 0.f, 0.f, 0.f);
            if (gr < NN)
                v = *reinterpret_cast<const float4*>(X + (size_t)gr * K + kt + c4 * 4);
            if (BN) {
                int kk = kt + c4 * 4;
                v.x = fmaxf(fmaf(v.x, sS[kk + 0], sT[kk + 0]), 0.f);
                v.y = fmaxf(fmaf(v.y, sS[kk + 1], sT[kk + 1]), 0.f);
                v.z = fmaxf(fmaf(v.z, sS[kk + 2], sT[kk + 2]), 0.f);
                v.w = fmaxf(fmaf(v.w, sS[kk + 3], sT[kk + 3]), 0.f);
            }
            reinterpret_cast<float4*>(sX)[i] = v;
        }
        __syncthreads();
#pragma unroll 8
        for (int k = 0; k < 64; k += 4) {
            float4 wv0 = *reinterpret_cast<const float4*>(sW + (k + 0) * NC + ct * 4);
            float4 wv1 = *reinterpret_cast<const float4*>(sW + (k + 1) * NC + ct * 4);
            float4 wv2 = *reinterpret_cast<const float4*>(sW + (k + 2) * NC + ct * 4);
            float4 wv3 = *reinterpret_cast<const float4*>(sW + (k + 3) * NC + ct * 4);
#pragma unroll
            for (int i = 0; i < 4; i++) {
                float4 xv = *reinterpret_cast<const float4*>(sX + (row0 + i) * 64 + k);
                acc[i][0] = fmaf(xv.x, wv0.x, acc[i][0]);
                acc[i][1] = fmaf(xv.x, wv0.y, acc[i][1]);
                acc[i][2] = fmaf(xv.x, wv0.z, acc[i][2]);
                acc[i][3] = fmaf(xv.x, wv0.w, acc[i][3]);
                acc[i][0] = fmaf(xv.y, wv1.x, acc[i][0]);
                acc[i][1] = fmaf(xv.y, wv1.y, acc[i][1]);
                acc[i][2] = fmaf(xv.y, wv1.z, acc[i][2]);
                acc[i][3] = fmaf(xv.y, wv1.w, acc[i][3]);
                acc[i][0] = fmaf(xv.z, wv2.x, acc[i][0]);
                acc[i][1] = fmaf(xv.z, wv2.y, acc[i][1]);
                acc[i][2] = fmaf(xv.z, wv2.z, acc[i][2]);
                acc[i][3] = fmaf(xv.z, wv2.w, acc[i][3]);
                acc[i][0] = fmaf(xv.w, wv3.x, acc[i][0]);
                acc[i][1] = fmaf(xv.w, wv3.y, acc[i][1]);
                acc[i][2] = fmaf(xv.w, wv3.z, acc[i][2]);
                acc[i][3] = fmaf(xv.w, wv3.w, acc[i][3]);
            }
        }
    }

    float4 a_s = *reinterpret_cast<const float4*>(asv + ct * 4);
    float4 a_d = *reinterpret_cast<const float4*>(adv + ct * 4);
#pragma unroll
    for (int i = 0; i < 4; i++) {
        int gr = r0 + row0 + i;
        float ps = acc[i][0] * a_s.x + acc[i][1] * a_s.y + acc[i][2] * a_s.z + acc[i][3] * a_s.w;
        float pd = acc[i][0] * a_d.x + acc[i][1] * a_d.y + acc[i][2] * a_d.z + acc[i][3] * a_d.w;
        ps += __shfl_xor_sync(0xffffffffu, ps, 1);
        pd += __shfl_xor_sync(0xffffffffu, pd, 1);
        ps += __shfl_xor_sync(0xffffffffu, ps, 2);
        pd += __shfl_xor_sync(0xffffffffu, pd, 2);
        ps += __shfl_xor_sync(0xffffffffu, ps, 4);
        pd += __shfl_xor_sync(0xffffffffu, pd, 4);
        if (gr < NN) {
            float4 o = make_float4(acc[i][0], acc[i][1], acc[i][2], acc[i][3]);
            *reinterpret_cast<float4*>(Hout + (size_t)gr * NC + ct * 4) = o;
            if ((ct & 7) == 0) {
                int head = (H == 2) ? (ct >> 3) : 0;
                d_es[gr * H + head] = ps;
                d_ed[gr * H + head] = pd;
            }
        }
    }
}

// -------- GAT aggregation: chunked warp-cooperative softmax + fused BN stats ------
__device__ __forceinline__ float lrelu(float x) { return fmaxf(x, 0.2f * x); }

template<int H>
__global__ void __launch_bounds__(512) agg_k(const float* __restrict__ Hm,
                                             const float* __restrict__ bias,
                                             float* __restrict__ out,
                                             float* __restrict__ accOut) {
    __shared__ float red[16][128];
    const unsigned FULL = 0xffffffffu;
    int w = threadIdx.x >> 5;
    int l = threadIdx.x & 31;
    int node = blockIdx.x * 16 + w;

    if (H == 2) {
        float o0 = 0.f, o1 = 0.f;
        if (node < NN) {
            int beg = __ldg(&d_rowptr[node]);
            int end = __ldg(&d_rowptr[node + 1]);
            const float2 edv = reinterpret_cast<const float2*>(d_ed)[node];
            const float2* es2 = reinterpret_cast<const float2*>(d_es);
            float dn0 = 0.f, dn1 = 0.f, a0 = 0.f, a1 = 0.f;
            for (int base = beg; base < end; base += 32) {
                int j = base + l;
                int s = 0;
                float p0 = 0.f, p1 = 0.f;
                if (j < end) {
                    s = __ldg(&d_col[j]);
                    float2 e = __ldg(&es2[s]);
                    p0 = __expf(lrelu(e.x + edv.x));
                    p1 = __expf(lrelu(e.y + edv.y));
                }
                dn0 += p0;  dn1 += p1;
                int cnt = min(end - base, 32);
#pragma unroll 4
                for (int t = 0; t < cnt; t++) {
                    int   ss = __shfl_sync(FULL, s, t);
                    float q0 = __shfl_sync(FULL, p0, t);
                    float q1 = __shfl_sync(FULL, p1, t);
                    const float* hr = Hm + (size_t)ss * 64;
                    a0 = fmaf(q0, __ldg(hr + l), a0);
                    a1 = fmaf(q1, __ldg(hr + 32 + l), a1);
                }
            }
#pragma unroll
            for (int o = 16; o; o >>= 1) {
                dn0 += __shfl_xor_sync(FULL, dn0, o);
                dn1 += __shfl_xor_sync(FULL, dn1, o);
            }
            o0 = a0 / (dn0 + 1e-16f) + __ldg(bias + l);
            o1 = a1 / (dn1 + 1e-16f) + __ldg(bias + 32 + l);
            out[(size_t)node * 64 + l]      = o0;
            out[(size_t)node * 64 + 32 + l] = o1;
        }
        red[w][l]      = o0;
        red[w][32 + l] = o1;
        red[w][64 + l] = o0 * o0;
        red[w][96 + l] = o1 * o1;
        __syncthreads();
        if (threadIdx.x < 128) {
            float s = 0.f;
#pragma unroll
            for (int i = 0; i < 16; i++) s += red[i][threadIdx.x];
            atomicAdd(&accOut[threadIdx.x], s);
        }
    } else {
        float o = 0.f;
        if (node < NN) {
            int beg = __ldg(&d_rowptr[node]);
            int end = __ldg(&d_rowptr[node + 1]);
            float edv = d_ed[node];
            float dn = 0.f, a = 0.f;
            for (int base = beg; base < end; base += 32) {
                int j = base + l;
                int s = 0;
                float p = 0.f;
                if (j < end) {
                    s = __ldg(&d_col[j]);
                    p = __expf(lrelu(__ldg(&d_es[s]) + edv));
                }
                dn += p;
                int cnt = min(end - base, 32);
#pragma unroll 4
                for (int t = 0; t < cnt; t++) {
                    int   ss = __shfl_sync(FULL, s, t);
                    float q  = __shfl_sync(FULL, p, t);
                    a = fmaf(q, __ldg(Hm + (size_t)ss * 32 + l), a);
                }
            }
#pragma unroll
            for (int o2 = 16; o2; o2 >>= 1)
                dn += __shfl_xor_sync(FULL, dn, o2);
            o = a / (dn + 1e-16f) + __ldg(bias + l);
            out[(size_t)node * 32 + l] = o;
        }
        red[w][l]      = o;
        red[w][32 + l] = o * o;
        __syncthreads();
        if (threadIdx.x < 64) {
            float s = 0.f;
#pragma unroll
            for (int i = 0; i < 16; i++) s += red[i][threadIdx.x];
            atomicAdd(&accOut[threadIdx.x], s);
        }
    }
}

// final BN apply + ReLU -> out
__global__ void bnapply3_k(const float* __restrict__ X, const float* __restrict__ acc,
                           const float* __restrict__ g, const float* __restrict__ be,
                           float* __restrict__ Y) {
    int idx = blockIdx.x * 256 + threadIdx.x;
    if (idx >= NN * 32) return;
    int c = idx & 31;
    float mu  = acc[c] * (1.f / NN);
    float var = fmaf(-mu, mu, acc[32 + c] * (1.f / NN));
    float y = (X[idx] - mu) * rsqrtf(var + EPS) * g[c] + be[c];
    Y[idx] = fmaxf(y, 0.f);
}

// ---------------- launch ----------------
static inline int cdiv(int a, int b) { return (a + b - 1) / b; }

extern "C" void kernel_launch(void* const* d_in, const int* in_sizes, int n_in,
                              void* d_out, int out_size) {
    const float* x   = (const float*)d_in[0];
    const float* W1  = (const float*)d_in[1];
    const float* as1 = (const float*)d_in[2];
    const float* ad1 = (const float*)d_in[3];
    const float* b1  = (const float*)d_in[4];
    const float* g1  = (const float*)d_in[5];
    const float* be1 = (const float*)d_in[6];
    const float* W2  = (const float*)d_in[7];
    const float* as2 = (const float*)d_in[8];
    const float* ad2 = (const float*)d_in[9];
    const float* b2  = (const float*)d_in[10];
    const float* g2  = (const float*)d_in[11];
    const float* be2 = (const float*)d_in[12];
    const float* W3  = (const float*)d_in[13];
    const float* as3 = (const float*)d_in[14];
    const float* ad3 = (const float*)d_in[15];
    const float* b3  = (const float*)d_in[16];
    const float* g3  = (const float*)d_in[17];
    const float* be3 = (const float*)d_in[18];
    const int*   ei  = (const int*)d_in[19];
    const int* esrc = ei;
    const int* edst = ei + EE;

    float* bufA; cudaGetSymbolAddress((void**)&bufA, d_bufA);
    float* bufB; cudaGetSymbolAddress((void**)&bufB, d_bufB);
    float* bufC; cudaGetSymbolAddress((void**)&bufC, d_bufC);
    float* bnac; cudaGetSymbolAddress((void**)&bnac, d_bnacc);
    int*   cntp; cudaGetSymbolAddress((void**)&cntp, d_cnt);
    float* outp = (float*)d_out;

    const int aggBlocks = cdiv(NN, 16);   // 3125

    cudaMemsetAsync(cntp, 0, NN * sizeof(int));
    cudaMemsetAsync(bnac, 0, 320 * sizeof(float));

    // CSR build; gemm1 interleaved (independent of CSR)
    count_k<<<cdiv(ETOT, 256), 256>>>(edst);
    scan1_k<<<NB, 1024>>>();
    gemm_k<128, 64, false, 2><<<cdiv(NN, 64), 256>>>(
        x, W1, as1, ad1, nullptr, nullptr, nullptr, bufB);
    scan2_k<<<1, 64>>>();
    scan3_k<<<cdiv(NN, 256), 256>>>();
    scatter_k<<<cdiv(ETOT, 256), 256>>>(esrc, edst);

    // layer 1 aggregation (+BN1 stats)
    agg_k<2><<<aggBlocks, 512>>>(bufB, b1, bufC, bnac + 0);

    // layer 2 (BN1+ReLU fused into X staging)
    gemm_k<64, 64, true, 2><<<cdiv(NN, 64), 256>>>(
        bufC, W2, as2, ad2, bnac + 0, g1, be1, bufB);
    agg_k<2><<<aggBlocks, 512>>>(bufB, b2, bufC, bnac + 128);

    // layer 3 (BN2+ReLU fused into X staging)
    gemm_k<64, 32, true, 1><<<cdiv(NN, 128), 256>>>(
        bufC, W3, as3, ad3, bnac + 128, g2, be2, bufA);
    agg_k<1><<<aggBlocks, 512>>>(bufA, b3, bufC, bnac + 256);
    bnapply3_k<<<cdiv(NN * 32, 256), 256>>>(bufC, bnac + 256, g3, be3, outp);
}

// round 8
// speedup vs baseline: 1.2362x; 1.0437x over previous
#include <cuda_runtime.h>
#include <cuda_bf16.h>
#include <cuda_fp16.h>
#include <math.h>

#define NN 50000
#define EE 800000
#define ETOT (EE + NN)
#define NB 49              // ceil(NN/1024)
#define EPS 1e-5f

// ---------------- device scratch ----------------
__device__ float   d_bufA[NN * 64];
__device__ float   d_bufB[NN * 64];
__device__ float   d_bufC[NN * 64];
__device__ __half2 d_h16[NN * 32];   // fp16 copy of H (64 cols) / first 16 cols used for NC=32
__device__ float   d_es[NN * 2];
__device__ float   d_ed[NN * 2];
__device__ float   d_pe[ETOT * 2];   // per-edge exp(lrelu(.)) (float2 for H2, float for H1)
__device__ int     d_cnt[NN];
__device__ int     d_scan[NN];
__device__ int     d_rowptr[NN + 1];
__device__ int     d_cursor[NN];
__device__ int2    d_cr[ETOT];       // (src, dst) per CSR slot
__device__ int     d_btot[NB];
__device__ int     d_boff[NB];
__device__ float   d_bnacc[320];     // L1:[sum64|sq64] L2:[sum64|sq64] L3:[sum32|sq32]

// ---------------- CSR build ----------------
__global__ void count_k(const int* __restrict__ dst) {
    int i = blockIdx.x * 256 + threadIdx.x;
    if (i >= ETOT) return;
    int d = (i < EE) ? __ldg(&dst[i]) : (i - EE);
    atomicAdd(&d_cnt[d], 1);
}

__global__ void scan1_k() {
    __shared__ int wsum[32];
    int g = blockIdx.x * 1024 + threadIdx.x;
    int lane = threadIdx.x & 31, wid = threadIdx.x >> 5;
    int v = (g < NN) ? d_cnt[g] : 0;
    int x = v;
#pragma unroll
    for (int o = 1; o < 32; o <<= 1) {
        int t = __shfl_up_sync(0xffffffffu, x, o);
        if (lane >= o) x += t;
    }
    if (lane == 31) wsum[wid] = x;
    __syncthreads();
    if (wid == 0) {
        int w = wsum[lane];
#pragma unroll
        for (int o = 1; o < 32; o <<= 1) {
            int t = __shfl_up_sync(0xffffffffu, w, o);
            if (lane >= o) w += t;
        }
        wsum[lane] = w;
    }
    __syncthreads();
    int incl = x + (wid ? wsum[wid - 1] : 0);
    if (g < NN) d_scan[g] = incl;
    if (threadIdx.x == 1023) d_btot[blockIdx.x] = incl;
}

__global__ void scan2_k() {   // 64 threads, NB=49
    int t = threadIdx.x;
    int lane = t & 31, w = t >> 5;
    int v = (t < NB) ? d_btot[t] : 0;
    int x = v;
#pragma unroll
    for (int o = 1; o < 32; o <<= 1) {
        int s = __shfl_up_sync(0xffffffffu, x, o);
        if (lane >= o) x += s;
    }
    __shared__ int s0;
    if (w == 0 && lane == 31) s0 = x;
    __syncthreads();
    int incl = x + (w ? s0 : 0);
    if (t < NB) d_boff[t] = incl - v;
}

__global__ void scan3_k() {
    int i = blockIdx.x * 256 + threadIdx.x;
    if (i >= NN) return;
    int incl = d_scan[i] + d_boff[i >> 10];
    int excl = incl - d_cnt[i];
    d_rowptr[i] = excl;
    d_cursor[i] = excl;
    if (i == NN - 1) d_rowptr[NN] = incl;
}

__global__ void scatter_k(const int* __restrict__ src, const int* __restrict__ dst) {
    int i = blockIdx.x * 256 + threadIdx.x;
    if (i >= ETOT) return;
    int s, d;
    if (i < EE) { s = __ldg(&src[i]); d = __ldg(&dst[i]); }
    else        { s = i - EE; d = s; }
    int pos = atomicAdd(&d_cursor[d], 1);
    d_cr[pos] = make_int2(s, d);
}

// ------- fused GEMM (R4-proven scalar core) + BN input + es/ed + fp16-copy epilogue -
template<int K, int NC, bool BN, int H>
__global__ void __launch_bounds__(256) gemm_k(
    const float* __restrict__ X, const float* __restrict__ W,
    const float* __restrict__ asv, const float* __restrict__ adv,
    const float* __restrict__ accIn, const float* __restrict__ g,
    const float* __restrict__ be, float* __restrict__ Hout)
{
    constexpr int CT  = NC / 4;        // 16 (NC=64) or 8 (NC=32)
    constexpr int RT  = 256 / CT;      // 16 or 32
    constexpr int RPB = RT * 4;        // 64 or 128 rows per block
    __shared__ float sW[64 * NC];
    __shared__ float sX[RPB * 64];
    __shared__ float sS[BN ? K : 1];
    __shared__ float sT[BN ? K : 1];

    if (BN) {
        if (threadIdx.x < K) {
            float mu  = accIn[threadIdx.x] * (1.f / NN);
            float var = fmaf(-mu, mu, accIn[K + threadIdx.x] * (1.f / NN));
            float sc  = rsqrtf(var + EPS) * g[threadIdx.x];
            sS[threadIdx.x] = sc;
            sT[threadIdx.x] = be[threadIdx.x] - mu * sc;
        }
    }
    const int ct = threadIdx.x % CT;
    const int rt = threadIdx.x / CT;
    const int r0 = blockIdx.x * RPB;
    const int row0 = rt * 4;
    float acc[4][4] = {};

    for (int kt = 0; kt < K; kt += 64) {
        __syncthreads();
#pragma unroll
        for (int i = threadIdx.x; i < 64 * NC / 4; i += 256) {
            reinterpret_cast<float4*>(sW)[i] =
                __ldg(reinterpret_cast<const float4*>(W) + (size_t)kt * (NC / 4) + i);
        }
#pragma unroll
        for (int i = threadIdx.x; i < RPB * 16; i += 256) {
            int r = i >> 4, c4 = i & 15;
            int gr = r0 + r;
            float4 v = make_float4(0.f, 0.f, 0.f, 0.f);
            if (gr < NN)
                v = *reinterpret_cast<const float4*>(X + (size_t)gr * K + kt + c4 * 4);
            if (BN) {
                int kk = kt + c4 * 4;
                v.x = fmaxf(fmaf(v.x, sS[kk + 0], sT[kk + 0]), 0.f);
                v.y = fmaxf(fmaf(v.y, sS[kk + 1], sT[kk + 1]), 0.f);
                v.z = fmaxf(fmaf(v.z, sS[kk + 2], sT[kk + 2]), 0.f);
                v.w = fmaxf(fmaf(v.w, sS[kk + 3], sT[kk + 3]), 0.f);
            }
            reinterpret_cast<float4*>(sX)[i] = v;
        }
        __syncthreads();
#pragma unroll 8
        for (int k = 0; k < 64; k += 4) {
            float4 wv0 = *reinterpret_cast<const float4*>(sW + (k + 0) * NC + ct * 4);
            float4 wv1 = *reinterpret_cast<const float4*>(sW + (k + 1) * NC + ct * 4);
            float4 wv2 = *reinterpret_cast<const float4*>(sW + (k + 2) * NC + ct * 4);
            float4 wv3 = *reinterpret_cast<const float4*>(sW + (k + 3) * NC + ct * 4);
#pragma unroll
            for (int i = 0; i < 4; i++) {
                float4 xv = *reinterpret_cast<const float4*>(sX + (row0 + i) * 64 + k);
                acc[i][0] = fmaf(xv.x, wv0.x, acc[i][0]);
                acc[i][1] = fmaf(xv.x, wv0.y, acc[i][1]);
                acc[i][2] = fmaf(xv.x, wv0.z, acc[i][2]);
                acc[i][3] = fmaf(xv.x, wv0.w, acc[i][3]);
                acc[i][0] = fmaf(xv.y, wv1.x, acc[i][0]);
                acc[i][1] = fmaf(xv.y, wv1.y, acc[i][1]);
                acc[i][2] = fmaf(xv.y, wv1.z, acc[i][2]);
                acc[i][3] = fmaf(xv.y, wv1.w, acc[i][3]);
                acc[i][0] = fmaf(xv.z, wv2.x, acc[i][0]);
                acc[i][1] = fmaf(xv.z, wv2.y, acc[i][1]);
                acc[i][2] = fmaf(xv.z, wv2.z, acc[i][2]);
                acc[i][3] = fmaf(xv.z, wv2.w, acc[i][3]);
                acc[i][0] = fmaf(xv.w, wv3.x, acc[i][0]);
                acc[i][1] = fmaf(xv.w, wv3.y, acc[i][1]);
                acc[i][2] = fmaf(xv.w, wv3.z, acc[i][2]);
                acc[i][3] = fmaf(xv.w, wv3.w, acc[i][3]);
            }
        }
    }

    float4 a_s = *reinterpret_cast<const float4*>(asv + ct * 4);
    float4 a_d = *reinterpret_cast<const float4*>(adv + ct * 4);
#pragma unroll
    for (int i = 0; i < 4; i++) {
        int gr = r0 + row0 + i;
        float ps = acc[i][0] * a_s.x + acc[i][1] * a_s.y + acc[i][2] * a_s.z + acc[i][3] * a_s.w;
        float pd = acc[i][0] * a_d.x + acc[i][1] * a_d.y + acc[i][2] * a_d.z + acc[i][3] * a_d.w;
        ps += __shfl_xor_sync(0xffffffffu, ps, 1);
        pd += __shfl_xor_sync(0xffffffffu, pd, 1);
        ps += __shfl_xor_sync(0xffffffffu, ps, 2);
        pd += __shfl_xor_sync(0xffffffffu, pd, 2);
        ps += __shfl_xor_sync(0xffffffffu, ps, 4);
        pd += __shfl_xor_sync(0xffffffffu, pd, 4);
        if (gr < NN) {
            float4 o = make_float4(acc[i][0], acc[i][1], acc[i][2], acc[i][3]);
            *reinterpret_cast<float4*>(Hout + (size_t)gr * NC + ct * 4) = o;
            // fp16 copy for the aggregation gather
            int hbase = (NC == 64) ? (gr * 32 + ct * 2) : (gr * 16 + ct * 2);
            d_h16[hbase]     = __floats2half2_rn(acc[i][0], acc[i][1]);
            d_h16[hbase + 1] = __floats2half2_rn(acc[i][2], acc[i][3]);
            if ((ct & 7) == 0) {
                int head = (H == 2) ? (ct >> 3) : 0;
                d_es[gr * H + head] = ps;
                d_ed[gr * H + head] = pd;
            }
        }
    }
}

// ---------------- edge-parallel exp pass ----------------
__device__ __forceinline__ float lrelu(float x) { return fmaxf(x, 0.2f * x); }

template<int H>
__global__ void exp_k() {
    int i = blockIdx.x * 256 + threadIdx.x;
    if (i >= ETOT) return;
    int2 cr = __ldg(&d_cr[i]);
    if (H == 2) {
        const float2* es2 = reinterpret_cast<const float2*>(d_es);
        const float2* ed2 = reinterpret_cast<const float2*>(d_ed);
        float2 e = __ldg(&es2[cr.x]);
        float2 d = __ldg(&ed2[cr.y]);
        float2 p;
        p.x = __expf(lrelu(e.x + d.x));
        p.y = __expf(lrelu(e.y + d.y));
        reinterpret_cast<float2*>(d_pe)[i] = p;
    } else {
        d_pe[i] = __expf(lrelu(__ldg(&d_es[cr.x]) + __ldg(&d_ed[cr.y])));
    }
}

// -------- GAT aggregation (warp/node, fp16 gather) + fused BN stats --------------
template<int H>
__global__ void __launch_bounds__(512) agg_k(const float* __restrict__ bias,
                                             float* __restrict__ out,
                                             float* __restrict__ accOut) {
    __shared__ float red[16][128];
    int w = threadIdx.x >> 5;
    int l = threadIdx.x & 31;
    int node = blockIdx.x * 16 + w;

    if (H == 2) {
        float o0 = 0.f, o1 = 0.f;
        if (node < NN) {
            int beg = __ldg(&d_rowptr[node]);
            int end = __ldg(&d_rowptr[node + 1]);
            const float2* pe2 = reinterpret_cast<const float2*>(d_pe);
            float dn0 = 0.f, dn1 = 0.f, a0 = 0.f, a1 = 0.f;
#pragma unroll 4
            for (int j = beg; j < end; j++) {
                int s = __ldg(&d_cr[j]).x;
                float2 p = __ldg(&pe2[j]);
                __half2 hh = __ldg(&d_h16[s * 32 + l]);   // lane l -> cols 2l,2l+1
                float2 hf = __half22float2(hh);
                float pp = (l < 16) ? p.x : p.y;
                a0 = fmaf(pp, hf.x, a0);
                a1 = fmaf(pp, hf.y, a1);
                dn0 += p.x;  dn1 += p.y;
            }
            float dn = (l < 16) ? dn0 : dn1;
            float inv = 1.f / (dn + 1e-16f);
            float2 bb = __ldg(reinterpret_cast<const float2*>(bias) + l);
            o0 = a0 * inv + bb.x;
            o1 = a1 * inv + bb.y;
            reinterpret_cast<float2*>(out + (size_t)node * 64)[l] =
                make_float2(o0, o1);
        }
        red[w][2 * l]          = o0;
        red[w][2 * l + 1]      = o1;
        red[w][64 + 2 * l]     = o0 * o0;
        red[w][64 + 2 * l + 1] = o1 * o1;
        __syncthreads();
        if (threadIdx.x < 128) {
            float s = 0.f;
#pragma unroll
            for (int i = 0; i < 16; i++) s += red[i][threadIdx.x];
            atomicAdd(&accOut[threadIdx.x], s);
        }
    } else {
        const __half* h16h = reinterpret_cast<const __half*>(d_h16);
        float o = 0.f;
        if (node < NN) {
            int beg = __ldg(&d_rowptr[node]);
            int end = __ldg(&d_rowptr[node + 1]);
            float dn = 0.f, a = 0.f;
#pragma unroll 4
            for (int j = beg; j < end; j++) {
                int s = __ldg(&d_cr[j]).x;
                float p = __ldg(&d_pe[j]);
                float hv = __half2float(__ldg(&h16h[s * 32 + l]));
                a = fmaf(p, hv, a);
                dn += p;
            }
            o = a / (dn + 1e-16f) + __ldg(bias + l);
            out[(size_t)node * 32 + l] = o;
        }
        red[w][l]      = o;
        red[w][32 + l] = o * o;
        __syncthreads();
        if (threadIdx.x < 64) {
            float s = 0.f;
#pragma unroll
            for (int i = 0; i < 16; i++) s += red[i][threadIdx.x];
            atomicAdd(&accOut[threadIdx.x], s);
        }
    }
}

// final BN apply + ReLU -> out
__global__ void bnapply3_k(const float* __restrict__ X, const float* __restrict__ acc,
                           const float* __restrict__ g, const float* __restrict__ be,
                           float* __restrict__ Y) {
    int idx = blockIdx.x * 256 + threadIdx.x;
    if (idx >= NN * 32) return;
    int c = idx & 31;
    float mu  = acc[c] * (1.f / NN);
    float var = fmaf(-mu, mu, acc[32 + c] * (1.f / NN));
    float y = (X[idx] - mu) * rsqrtf(var + EPS) * g[c] + be[c];
    Y[idx] = fmaxf(y, 0.f);
}

// ---------------- launch ----------------
static inline int cdiv(int a, int b) { return (a + b - 1) / b; }

extern "C" void kernel_launch(void* const* d_in, const int* in_sizes, int n_in,
                              void* d_out, int out_size) {
    const float* x   = (const float*)d_in[0];
    const float* W1  = (const float*)d_in[1];
    const float* as1 = (const float*)d_in[2];
    const float* ad1 = (const float*)d_in[3];
    const float* b1  = (const float*)d_in[4];
    const float* g1  = (const float*)d_in[5];
    const float* be1 = (const float*)d_in[6];
    const float* W2  = (const float*)d_in[7];
    const float* as2 = (const float*)d_in[8];
    const float* ad2 = (const float*)d_in[9];
    const float* b2  = (const float*)d_in[10];
    const float* g2  = (const float*)d_in[11];
    const float* be2 = (const float*)d_in[12];
    const float* W3  = (const float*)d_in[13];
    const float* as3 = (const float*)d_in[14];
    const float* ad3 = (const float*)d_in[15];
    const float* b3  = (const float*)d_in[16];
    const float* g3  = (const float*)d_in[17];
    const float* be3 = (const float*)d_in[18];
    const int*   ei  = (const int*)d_in[19];
    const int* esrc = ei;
    const int* edst = ei + EE;

    float* bufA; cudaGetSymbolAddress((void**)&bufA, d_bufA);
    float* bufB; cudaGetSymbolAddress((void**)&bufB, d_bufB);
    float* bufC; cudaGetSymbolAddress((void**)&bufC, d_bufC);
    float* bnac; cudaGetSymbolAddress((void**)&bnac, d_bnacc);
    int*   cntp; cudaGetSymbolAddress((void**)&cntp, d_cnt);
    float* outp = (float*)d_out;

    const int aggBlocks  = cdiv(NN, 16);     // 3125
    const int edgeBlocks = cdiv(ETOT, 256);  // 3321

    cudaMemsetAsync(cntp, 0, NN * sizeof(int));
    cudaMemsetAsync(bnac, 0, 320 * sizeof(float));

    // CSR build; gemm1 interleaved (independent of CSR)
    count_k<<<edgeBlocks, 256>>>(edst);
    scan1_k<<<NB, 1024>>>();
    gemm_k<128, 64, false, 2><<<cdiv(NN, 64), 256>>>(
        x, W1, as1, ad1, nullptr, nullptr, nullptr, bufB);
    scan2_k<<<1, 64>>>();
    scan3_k<<<cdiv(NN, 256), 256>>>();
    scatter_k<<<edgeBlocks, 256>>>(esrc, edst);

    // layer 1
    exp_k<2><<<edgeBlocks, 256>>>();
    agg_k<2><<<aggBlocks, 512>>>(b1, bufC, bnac + 0);

    // layer 2 (BN1+ReLU fused into X staging)
    gemm_k<64, 64, true, 2><<<cdiv(NN, 64), 256>>>(
        bufC, W2, as2, ad2, bnac + 0, g1, be1, bufB);
    exp_k<2><<<edgeBlocks, 256>>>();
    agg_k<2><<<aggBlocks, 512>>>(b2, bufC, bnac + 128);

    // layer 3 (BN2+ReLU fused into X staging)
    gemm_k<64, 32, true, 1><<<cdiv(NN, 128), 256>>>(
        bufC, W3, as3, ad3, bnac + 128, g2, be2, bufA);
    exp_k<1><<<edgeBlocks, 256>>>();
    agg_k<1><<<aggBlocks, 512>>>(b3, bufC, bnac + 256);
    bnapply3_k<<<cdiv(NN * 32, 256), 256>>>(bufC, bnac + 256, g3, be3, outp);
}